// round 16
// baseline (speedup 1.0000x reference)
#include <cuda_runtime.h>
#include <stdint.h>
#include <math.h>

#define HW    65536
#define EE    256
#define GG    512
#define NCC   16
#define NB    296

// ---- scratch layout (floats), all regions write-once per launch ----
#define S_PART 0            // segsum partials [3][4][129][384] = 594432
#define S_GLP  594432       // glob partials [3][4][384] = 4608
#define S_ACNT 599040       // area counts (int) [4][129] pad 1024
#define S_AF   600064       // allfv  [512][768] = 393216
#define S_EM   993280       // emb    [512][256] = 131072
#define S_CP   1124352      // comp   [4][16] pad 1024
#define S_HH4  1125376      // hidden [4][512][256] = 524288
#define S_RW   1649664      // rw     [3][512][64] = 98304
#define S_OB   2534400      // ob     [3][4][256] = 3072
#define S_OW   2537472      // obwo   [3][4][512] = 6144
#define S_OE   2543616      // post-relu out_exprs[0] copy = 262144
#define P_EMB  2805760      // emb split-K partials 4*131072 = 524288
#define P_RW   3330048      // rw partials 24*32768 = 786432
#define P_GEN  4116480      // genes partials 4*131072 = 524288
#define P_KV   4640768      // kf/vf partials 12*131072 = 1572864
#define SCRATCH_FLOATS 6213632

__device__ float g_scratch[SCRATCH_FLOATS];

// ---- d_out layout (floats) ----
#define O_OCT  0
#define O_OE0  8192
#define O_OCTE 794624
#define O_GH   802816
#define O_CMP  933888
#define O_ARE  933952

// ============================================================
// software grid barrier (monotonic epochs; all NB blocks resident)
// ============================================================
__device__ unsigned long long g_bar_arrive = 0ULL;
__device__ volatile unsigned long long g_bar_release = 0ULL;

__device__ __forceinline__ void grid_bar()
{
    __syncthreads();
    __threadfence();
    if (threadIdx.x == 0) {
        unsigned long long t = atomicAdd(&g_bar_arrive, 1ULL);
        unsigned long long epoch = t / NB + 1ULL;
        if ((t % NB) == (unsigned long long)(NB - 1)) {
            g_bar_release = epoch;
            __threadfence();
        } else {
            while (g_bar_release < epoch) { }
            __threadfence();
        }
    }
    __syncthreads();
}

// ============================================================
// segsum helpers (cp.async)
// ============================================================
#define W2_T0  4128
#define W2_T1  5184
#define W2_I0  6240
#define W2_I1  6272
#define W2_SZ  6304
#define SEG3_SMEM_BYTES (8 * W2_SZ * 4)

__device__ __forceinline__ uint32_t smem_u32(const void* p)
{
    uint32_t a;
    asm("{ .reg .u64 t; cvta.to.shared.u64 t, %1; cvt.u32.u64 %0, t; }"
        : "=r"(a) : "l"(p));
    return a;
}
__device__ __forceinline__ void cpa4(uint32_t dst, const void* src)
{
    asm volatile("cp.async.ca.shared.global [%0], [%1], 4;" :: "r"(dst), "l"(src));
}
#define CPA_COMMIT() asm volatile("cp.async.commit_group;")
#define CPA_WAIT1()  asm volatile("cp.async.wait_group 1;")
#define CPA_WAIT0()  asm volatile("cp.async.wait_group 0;")

// ============================================================
// segsum (unchanged: ~124us, DRAM-bound)
// ============================================================
__global__ void __launch_bounds__(256, 1)
segsum3_kernel(const float* __restrict__ hd1,
               const float* __restrict__ h1,
               const int* __restrict__ mask,
               float* __restrict__ partial,
               float* __restrict__ globpart)
{
    extern __shared__ float smem[];
    int cg = blockIdx.x, b = blockIdx.y, ps = blockIdx.z;
    int tid = threadIdx.x, lane = tid & 31, w = tid >> 5;

    for (int i = tid; i < 8 * W2_SZ; i += 256) smem[i] = 0.f;
    __syncthreads();

    const float* base = (cg < 8)
        ? hd1 + (((size_t)b * 256 + cg * 32) << 16)
        : h1  + (((size_t)b * 128 + (cg - 8) * 32) << 16);
    const int* mp = mask + ((size_t)b << 16);

    float* acc  = smem + w * W2_SZ;
    float* tile0 = smem + w * W2_SZ + W2_T0;
    float* tile1 = smem + w * W2_SZ + W2_T1;
    int*   ids0 = (int*)(smem + w * W2_SZ + W2_I0);
    int*   ids1 = (int*)(smem + w * W2_SZ + W2_I1);
    uint32_t tB0 = smem_u32(tile0), tB1 = smem_u32(tile1);
    uint32_t iB0 = smem_u32(ids0),  iB1 = smem_u32(ids1);

    int L = lane * 129;
    int T = lane * 33;
    float tot = 0.f;

    int tb = ps * 683;
    int te = (ps < 2) ? tb + 683 : 2048;
    int t0 = tb + w;
    int cnt = (t0 < te) ? (te - t0 + 7) / 8 : 0;

#define SEG_PREFETCH(tt, TB, IB)                                        \
    do {                                                                \
        const float* cp_ = base + (tt) * 32 + lane;                     \
        uint32_t td_ = (TB) + lane * 4;                                 \
        _Pragma("unroll")                                               \
        for (int c_ = 0; c_ < 32; c_++)                                 \
            cpa4(td_ + c_ * (33 * 4), cp_ + ((size_t)c_ << 16));        \
        cpa4((IB) + lane * 4, mp + (tt) * 32 + lane);                   \
    } while (0)

    if (cnt > 0) { SEG_PREFETCH(t0, tB0, iB0); CPA_COMMIT(); }

    for (int i = 0; i < cnt; i++) {
        int cur = i & 1;
        if (i + 1 < cnt) {
            int tn = t0 + (i + 1) * 8;
            if ((i + 1) & 1) SEG_PREFETCH(tn, tB1, iB1);
            else             SEG_PREFETCH(tn, tB0, iB0);
            CPA_COMMIT();
            CPA_WAIT1();
        } else {
            CPA_WAIT0();
        }
        __syncwarp();
        const float* tile = cur ? tile1 : tile0;
        const int*   ids  = cur ? ids1  : ids0;
#pragma unroll
        for (int p = 0; p < 32; p += 4) {
            int i0 = ids[p], i1 = ids[p + 1], i2 = ids[p + 2], i3 = ids[p + 3];
            float t0v = tile[T + p],     t1v = tile[T + p + 1];
            float t2v = tile[T + p + 2], t3v = tile[T + p + 3];
            tot += (t0v + t1v) + (t2v + t3v);
            bool u1 = (i1 != i0);
            bool u2 = (i2 != i0) && (i2 != i1);
            bool u3 = (i3 != i0) && (i3 != i1) && (i3 != i2);
            if (!u3) { if (i3 == i0) t0v += t3v; else if (i3 == i1) t1v += t3v; else t2v += t3v; }
            if (!u2) { if (i2 == i0) t0v += t2v; else t1v += t2v; }
            if (!u1) t0v += t1v;
            float a0 = acc[L + i0] + t0v;
            float a1 = u1 ? acc[L + i1] + t1v : 0.f;
            float a2 = u2 ? acc[L + i2] + t2v : 0.f;
            float a3 = u3 ? acc[L + i3] + t3v : 0.f;
            acc[L + i0] = a0;
            if (u1) acc[L + i1] = a1;
            if (u2) acc[L + i2] = a2;
            if (u3) acc[L + i3] = a3;
        }
        __syncwarp();
    }
#undef SEG_PREFETCH

    __syncwarp();
    ((float*)ids0)[lane] = tot;
    __syncthreads();

    if (tid < 32) {
        float s = 0.f;
#pragma unroll
        for (int ww = 0; ww < 8; ww++) s += smem[ww * W2_SZ + W2_I0 + tid];
        globpart[(size_t)(ps * 4 + b) * 384 + cg * 32 + tid] = s;
    }

    float* outp = partial + ((size_t)(ps * 4 + b) * 129 * 384) + cg * 32;
    for (int i = tid; i < 129 * 32; i += 256) {
        int cell = i >> 5, ch = i & 31;
        float s = 0.f;
#pragma unroll
        for (int ww = 0; ww < 8; ww++) s += smem[ww * W2_SZ + ch * 129 + cell];
        outp[(size_t)cell * 384 + ch] = s;
    }
}

// ============================================================
__global__ void zero_acnt(int* __restrict__ cnt)
{
    int i = threadIdx.x;
    if (i < 516) cnt[i] = 0;
}

__global__ void hist_kernel(const int* __restrict__ mask, int* __restrict__ cnt)
{
    int b = blockIdx.x, ch = blockIdx.y, tid = threadIdx.x;
    __shared__ int h[129];
    if (tid < 129) h[tid] = 0;
    __syncthreads();
    const int* mp = mask + ((size_t)b << 16) + ch * 4096;
    for (int i = tid; i < 4096; i += 256)
        atomicAdd(&h[mp[i]], 1);
    __syncthreads();
    if (tid < 129 && h[tid]) atomicAdd(&cnt[b * 129 + tid], h[tid]);
}

// ============================================================
// device GEMM tile: 64x64 output, BK=16, 4x4 microtile.
// Double-buffered smem (gs = 4096 floats): ONE __syncthreads per K-slab.
// ============================================================
__device__ void gemm_tile(const float* __restrict__ A, int lda,
                          const float* __restrict__ B, int ldb,
                          float* __restrict__ C, int ldc,
                          int K, int relu, int row0, int col0, float* gs)
{
    __syncthreads();   // protect smem vs previous job
    int tid = threadIdx.x;
    int tx = tid & 15, ty = tid >> 4;
    int arow = tid >> 2, ak4 = (tid & 3) * 4;
    int brow = tid >> 4, bc4 = (tid & 15) * 4;

    const float* Ap = A + (size_t)(row0 + arow) * lda + ak4;
    const float* Bp = B + (size_t)brow * ldb + col0 + bc4;

    float acc[4][4] = {};
    float4 av = *(const float4*)(Ap);
    float4 bv = *(const float4*)(Bp);
    int n = K >> 4;
    for (int i = 0; i < n; i++) {
        float* As = gs + (i & 1) * 2048;
        float* Bs = As + 1024;
        As[(ak4 + 0) * 64 + arow] = av.x;
        As[(ak4 + 1) * 64 + arow] = av.y;
        As[(ak4 + 2) * 64 + arow] = av.z;
        As[(ak4 + 3) * 64 + arow] = av.w;
        *(float4*)&Bs[brow * 64 + bc4] = bv;
        if (i + 1 < n) {
            av = *(const float4*)(Ap + (i + 1) * 16);
            bv = *(const float4*)(Bp + (size_t)((i + 1) * 16) * ldb);
        }
        __syncthreads();
#pragma unroll
        for (int k = 0; k < 16; k++) {
            float4 a = *(const float4*)&As[k * 64 + ty * 4];
            float4 b = *(const float4*)&Bs[k * 64 + tx * 4];
            acc[0][0] += a.x * b.x; acc[0][1] += a.x * b.y; acc[0][2] += a.x * b.z; acc[0][3] += a.x * b.w;
            acc[1][0] += a.y * b.x; acc[1][1] += a.y * b.y; acc[1][2] += a.y * b.z; acc[1][3] += a.y * b.w;
            acc[2][0] += a.z * b.x; acc[2][1] += a.z * b.y; acc[2][2] += a.z * b.z; acc[2][3] += a.z * b.w;
            acc[3][0] += a.w * b.x; acc[3][1] += a.w * b.y; acc[3][2] += a.w * b.z; acc[3][3] += a.w * b.w;
        }
    }
#pragma unroll
    for (int i = 0; i < 4; i++) {
        float4 v = make_float4(acc[i][0], acc[i][1], acc[i][2], acc[i][3]);
        if (relu) {
            v.x = fmaxf(v.x, 0.f); v.y = fmaxf(v.y, 0.f);
            v.z = fmaxf(v.z, 0.f); v.w = fmaxf(v.w, 0.f);
        }
        *(float4*)&C[(size_t)(row0 + ty * 4 + i) * ldc + col0 + tx * 4] = v;
    }
}

// ============================================================
// device N16 GEMM: 32 rows x 16 cols, K multiple of 64; buf = 2048 floats.
// ============================================================
__device__ void gemmN16_dev(const float* __restrict__ A, const float* __restrict__ B,
                            float* __restrict__ C, int K, int row0, float* buf)
{
    int tid = threadIdx.x;
    int r = tid >> 3, cg = tid & 7, c0 = cg * 2;
    float s0 = 0.f, s1 = 0.f;
    for (int kb = 0; kb < K; kb += 64) {
        __syncthreads();
        for (int i = tid; i < 2048; i += 256) {
            int rr = i >> 6, kk = i & 63;
            buf[i] = A[(size_t)(row0 + rr) * K + kb + kk];
        }
        __syncthreads();
        const float* ar = buf + r * 64;
#pragma unroll 4
        for (int k = 0; k < 64; k++) {
            float a = ar[k];
            s0 += a * B[(kb + k) * 16 + c0];
            s1 += a * B[(kb + k) * 16 + c0 + 1];
        }
    }
    C[(size_t)(row0 + r) * 16 + c0]     = s0;
    C[(size_t)(row0 + r) * 16 + c0 + 1] = s1;
    __syncthreads();
}

// ============================================================
__device__ void embp_comp_dev(const float* __restrict__ emb,
                              const float* __restrict__ w1, const float* __restrict__ w2,
                              float* __restrict__ comp, float* __restrict__ comp_out,
                              int b, float* xs)
{
    __syncthreads();
    int tid = threadIdx.x;
    float* ep = xs;
    float* t1 = xs + 256;
    float* t2 = xs + 512;
    float s0 = 0.f;
    for (int i = 0; i < 128; i++)
        s0 += emb[(size_t)(b * 128 + i) * EE + tid];
    ep[tid] = s0 * (1.f / 128.f);
    __syncthreads();
    float s = 0.f;
    for (int c = 0; c < EE; c++)
        s += ep[c] * w1[(size_t)c * EE + tid];
    t1[tid] = fmaxf(s, 0.f);
    __syncthreads();
    if (tid < NCC) {
        float s2 = 0.f;
        for (int j = 0; j < EE; j++)
            s2 += t1[j] * w2[(size_t)j * NCC + tid];
        t2[tid] = s2;
    }
    __syncthreads();
    if (tid == 0) {
        float m = t2[0];
        for (int o = 1; o < NCC; o++) m = fmaxf(m, t2[o]);
        float tot = 0.f;
        float e[NCC];
        for (int o = 0; o < NCC; o++) { e[o] = expf(t2[o] - m); tot += e[o]; }
        float inv = 1.f / tot;
        for (int o = 0; o < NCC; o++) {
            comp[b * NCC + o] = e[o] * inv;
            comp_out[b * NCC + o] = e[o] * inv;
        }
    }
    __syncthreads();
}

// ============================================================
__device__ void reduce_softmax_dev(const float* __restrict__ P, float* __restrict__ rw,
                                   int job, float* xs)
{
    __syncthreads();
    int tid = threadIdx.x;
    int row = job * 4 + (tid >> 6);
    int col = tid & 63;
    int br = row >> 9, lr = row & 511;
    const float* p = P + (size_t)br * 8 * 32768 + (size_t)lr * 64 + col;
    float s = 0.f;
#pragma unroll
    for (int j = 0; j < 8; j++) s += p[(size_t)j * 32768];

    int lane = tid & 31, half = (tid >> 5) & 1, r4 = tid >> 6;
    float* mm = xs;
    float* ss = xs + 8;
    float m = s;
    for (int o = 16; o; o >>= 1) m = fmaxf(m, __shfl_xor_sync(0xffffffffu, m, o));
    if (lane == 0) mm[r4 * 2 + half] = m;
    __syncthreads();
    m = fmaxf(mm[r4 * 2], mm[r4 * 2 + 1]);
    float e = expf(s - m);
    float t = e;
    for (int o = 16; o; o >>= 1) t += __shfl_xor_sync(0xffffffffu, t, o);
    if (lane == 0) ss[r4 * 2 + half] = t;
    __syncthreads();
    t = ss[r4 * 2] + ss[r4 * 2 + 1];
    rw[(size_t)row * 64 + col] = e / t;
    __syncthreads();
}

// ============================================================
// attention with fused kf/vf split-K reduce: reads P_KV partial pairs.
// pkv slice layout: (mat*6 + br*2 + kc) * 131072, element (kn*256 + ch).
// ============================================================
__device__ void attn_dev(const float* __restrict__ comp,
                         const float* __restrict__ ca_wq,
                         const float* __restrict__ pkv,
                         float* __restrict__ ob,
                         int b, int h, int br, float* xs)
{
    __syncthreads();
    int tid = threadIdx.x, lane = tid & 31, warp = tid >> 5;
    const float* wq = ca_wq + (size_t)br * 16 * EE;
    const float* k0 = pkv + (size_t)(br * 2 + 0) * 131072;
    const float* k1 = pkv + (size_t)(br * 2 + 1) * 131072;
    const float* v0 = pkv + (size_t)(6 + br * 2 + 0) * 131072;
    const float* v1 = pkv + (size_t)(6 + br * 2 + 1) * 131072;

    float* q   = xs;
    float* scv = xs + 32;
    float* r1  = xs + 544;
    float* prt = xs + 800;

    if (tid < 32) {
        float s = 0.f;
        for (int c = 0; c < NCC; c++)
            s += comp[b * NCC + c] * wq[(size_t)c * EE + h * 32 + tid];
        q[tid] = s * 0.17677669529663687f;
    }
    __syncthreads();

    for (int kk = 0; kk < 64; kk++) {
        int kn = warp * 64 + kk;
        size_t idx = (size_t)kn * EE + h * 32 + lane;
        float p = q[lane] * (k0[idx] + k1[idx]);
        for (int off = 16; off; off >>= 1) p += __shfl_down_sync(0xffffffff, p, off);
        if (lane == 0) scv[kn] = p;
    }
    __syncthreads();

    float m = fmaxf(scv[tid], scv[tid + 256]);
    r1[tid] = m; __syncthreads();
    for (int s = 128; s > 0; s >>= 1) { if (tid < s) r1[tid] = fmaxf(r1[tid], r1[tid + s]); __syncthreads(); }
    float maxv = r1[0]; __syncthreads();
    float e0 = expf(scv[tid] - maxv), e1 = expf(scv[tid + 256] - maxv);
    scv[tid] = e0; scv[tid + 256] = e1;
    r1[tid] = e0 + e1; __syncthreads();
    for (int s = 128; s > 0; s >>= 1) { if (tid < s) r1[tid] += r1[tid + s]; __syncthreads(); }
    float invs = 1.f / r1[0];

    float a = 0.f;
    for (int kn = warp; kn < 512; kn += 8) {
        size_t idx = (size_t)kn * EE + h * 32 + lane;
        a += scv[kn] * (v0[idx] + v1[idx]);
    }
    prt[warp * 32 + lane] = a;
    __syncthreads();
    if (tid < 32) {
        float s = 0.f;
        for (int w = 0; w < 8; w++) s += prt[w * 32 + tid];
        ob[((size_t)br * 4 + b) * EE + h * 32 + tid] = s * invs;
    }
    __syncthreads();
}

// ============================================================
__device__ void obwo_dev(const float* __restrict__ ob, const float* __restrict__ ca_wo,
                         float* __restrict__ obwo, int j, float* xs)
{
    __syncthreads();
    int idx = j >> 1, half = j & 1;
    int br = idx >> 2;
    int tid = threadIdx.x;
    xs[tid] = ob[(size_t)idx * EE + tid];
    __syncthreads();
    const float* wo = ca_wo + (size_t)br * EE * GG;
    int col = half * 256 + tid;
    float s = 0.f;
    for (int c = 0; c < EE; c++)
        s += xs[c] * wo[(size_t)c * GG + col];
    obwo[(size_t)idx * GG + col] = s;
    __syncthreads();
}

// ============================================================
// Persistent chain megakernel, 296 blocks (2 CTAs/SM), dbuf tiles.
// ============================================================
__global__ void __launch_bounds__(256, 2)
chain_mega(const float* __restrict__ ref_orig, const float* __restrict__ embed_w,
           const float* __restrict__ comp_w1, const float* __restrict__ comp_w2,
           const float* __restrict__ hist_w1, const float* __restrict__ hist_w2,
           const float* __restrict__ genes_w1, const float* __restrict__ genes_w2,
           const float* __restrict__ wref_w1, const float* __restrict__ wref_w2,
           const float* __restrict__ ca_wq, const float* __restrict__ ca_wk,
           const float* __restrict__ ca_wv, const float* __restrict__ ca_wo,
           float* __restrict__ g, float* __restrict__ out)
{
    __shared__ float gs[4096];
    __shared__ float xs[1088];
    int tid = threadIdx.x;
    const int* acnt = (const int*)(g + S_ACNT);

    // ---- finalize (allfv + area), 512 jobs ----
    for (int n = blockIdx.x; n < 512; n += NB) {
        int b = n >> 7, cell = n & 127;
        int a = acnt[b * 129 + cell + 1];
        if (tid == 0) out[O_ARE + n] = (float)a;
        float inva = 1.f / fmaxf((float)a, 1.f);
        const size_t PS = (size_t)4 * 129 * 384;
        size_t rp0 = (size_t)b * 129 * 384 + (size_t)(cell + 1) * 384;
        for (int j = tid; j < 768; j += 256) {
            float v;
            if (j < 384) {
                v = (g[S_PART + rp0 + j] + g[S_PART + rp0 + PS + j]
                   + g[S_PART + rp0 + 2 * PS + j]) * inva;
            } else {
                int c = j - 384;
                v = (g[S_GLP + (size_t)b * 384 + c] + g[S_GLP + (size_t)(4 + b) * 384 + c]
                   + g[S_GLP + (size_t)(8 + b) * 384 + c]) * (1.f / 65536.f);
            }
            g[S_AF + (size_t)n * 768 + j] = v;
        }
    }
    grid_bar();

    // ---- emb GEMM, split-K 4 (128 jobs) ----
    for (int j = blockIdx.x; j < 128; j += NB) {
        int kc = j >> 5, t = j & 31;
        gemm_tile(g + S_AF + kc * 192, 768, embed_w + (size_t)kc * 192 * 256, 256,
                  g + P_EMB + (size_t)kc * 131072, 256, 192, 0,
                  (t >> 2) * 64, (t & 3) * 64, gs);
    }
    grid_bar();

    // ---- emb reduce (512 jobs) ----
    for (int j = blockIdx.x; j < 512; j += NB) {
        int i = j * 256 + tid;
        g[S_EM + i] = g[P_EMB + i] + g[P_EMB + 131072 + i]
                    + g[P_EMB + 262144 + i] + g[P_EMB + 393216 + i];
    }
    grid_bar();

    // ---- hidden (128 jobs, K=256 direct, relu) + embp_comp (4 jobs) ----
    for (int j = blockIdx.x; j < 132; j += NB) {
        if (j < 128) {
            int zz = j >> 5, t = j & 31;
            const float* B = (zz == 0) ? hist_w1 : wref_w1 + (size_t)(zz - 1) * 65536;
            gemm_tile(g + S_EM, 256, B, 256, g + S_HH4 + (size_t)zz * 131072, 256,
                      256, 1, (t >> 2) * 64, (t & 3) * 64, gs);
        } else {
            embp_comp_dev(g + S_EM, comp_w1, comp_w2, g + S_CP, out + O_CMP, j - 128, xs);
        }
    }
    grid_bar();

    // ---- out_cell_type (16 jobs) + rw logits split-K 8 (192 jobs) ----
    for (int j = blockIdx.x; j < 208; j += NB) {
        if (j < 16) {
            gemmN16_dev(g + S_HH4, hist_w2, out + O_OCT, 256, j * 32, gs);
        } else {
            int q = j - 16;
            int br = q / 64, rr = q - br * 64, kc = rr >> 3, mt = rr & 7;
            gemm_tile(g + S_HH4 + (size_t)(1 + br) * 131072 + kc * 32, 256,
                      wref_w2 + (size_t)br * 16384 + (size_t)kc * 32 * 64, 64,
                      g + P_RW + (size_t)(br * 8 + kc) * 32768, 64, 32, 0,
                      mt * 64, 0, gs);
        }
    }
    grid_bar();

    // ---- rw reduce + softmax (384 jobs) ----
    for (int j = blockIdx.x; j < 384; j += NB)
        reduce_softmax_dev(g + P_RW, g + S_RW, j, xs);
    grid_bar();

    // ---- refw (192 jobs, K=64) -> out_exprs pre-relu ----
    for (int j = blockIdx.x; j < 192; j += NB) {
        int br = j / 64, t = j - br * 64;
        gemm_tile(g + S_RW + (size_t)br * 32768, 64, ref_orig, 512,
                  out + O_OE0 + (size_t)br * 262144, 512, 64, 0,
                  (t >> 3) * 64, (t & 7) * 64, gs);
    }
    grid_bar();

    // ---- kf/vf split-K 2 (384 jobs) -> P_KV partials ----
    for (int j = blockIdx.x; j < 384; j += NB) {
        int mat = j / 192, rr = j - mat * 192;
        int br = rr / 64, rr2 = rr - br * 64;
        int kc = rr2 >> 5, t = rr2 & 31;
        const float* B = (mat ? ca_wv : ca_wk) + (size_t)br * 131072 + (size_t)kc * 256 * 256;
        gemm_tile(out + O_OE0 + (size_t)br * 262144 + kc * 256, 512, B, 256,
                  g + P_KV + (size_t)(mat * 6 + br * 2 + kc) * 131072, 256,
                  256, 0, (t >> 2) * 64, (t & 3) * 64, gs);
    }
    grid_bar();

    // ---- attention (96 jobs), kf/vf reduce fused inline ----
    for (int j = blockIdx.x; j < 96; j += NB)
        attn_dev(g + S_CP, ca_wq, g + P_KV, g + S_OB,
                 j & 3, (j >> 2) & 7, j >> 5, xs);
    grid_bar();

    // ---- obwo (24 jobs) ----
    for (int j = blockIdx.x; j < 24; j += NB)
        obwo_dev(g + S_OB, ca_wo, g + S_OW, j, xs);
    grid_bar();

    // ---- addrelu (3072 jobs); branch0 copy to S_OE ----
    for (int j = blockIdx.x; j < 3072; j += NB) {
        int i = j * 256 + tid;
        int br = i >> 18;
        int rem = i & 262143;
        int gg2 = rem & 511, n = rem >> 9, b = n >> 7;
        float v = out[O_OE0 + i] + g[S_OW + (size_t)(br * 4 + b) * 512 + gg2];
        v = fmaxf(v, 0.f);
        out[O_OE0 + i] = v;
        if (br == 0) g[S_OE + rem] = v;
    }
    grid_bar();

    // ---- genes GEMM split-K 4 (128 jobs) ----
    for (int j = blockIdx.x; j < 128; j += NB) {
        int kc = j >> 5, t = j & 31;
        gemm_tile(g + S_OE + kc * 128, 512, genes_w1 + (size_t)kc * 128 * 256, 256,
                  g + P_GEN + (size_t)kc * 131072, 256, 128, 0,
                  (t >> 2) * 64, (t & 3) * 64, gs);
    }
    grid_bar();

    // ---- genes reduce + relu (512 jobs) ----
    for (int j = blockIdx.x; j < 512; j += NB) {
        int i = j * 256 + tid;
        float s = g[P_GEN + i] + g[P_GEN + 131072 + i]
                + g[P_GEN + 262144 + i] + g[P_GEN + 393216 + i];
        out[O_GH + i] = fmaxf(s, 0.f);
    }
    grid_bar();

    // ---- out_cell_type_expr (16 jobs) ----
    for (int j = blockIdx.x; j < 16; j += NB)
        gemmN16_dev(out + O_GH, genes_w2, out + O_OCTE, 256, j * 32, gs);
}

// ============================================================
extern "C" void kernel_launch(void* const* d_in, const int* in_sizes, int n_in,
                              void* d_out, int out_size)
{
    (void)in_sizes; (void)n_in; (void)out_size;
    const float* hd1      = (const float*)d_in[0];
    const float* h1       = (const float*)d_in[1];
    const float* ref_orig = (const float*)d_in[2];
    const float* embed_w  = (const float*)d_in[3];
    const float* comp_w1  = (const float*)d_in[4];
    const float* comp_w2  = (const float*)d_in[5];
    const float* hist_w1  = (const float*)d_in[6];
    const float* hist_w2  = (const float*)d_in[7];
    const float* genes_w1 = (const float*)d_in[8];
    const float* genes_w2 = (const float*)d_in[9];
    const float* wref_w1  = (const float*)d_in[10];
    const float* wref_w2  = (const float*)d_in[11];
    const float* ca_wq    = (const float*)d_in[12];
    const float* ca_wk    = (const float*)d_in[13];
    const float* ca_wv    = (const float*)d_in[14];
    const float* ca_wo    = (const float*)d_in[15];
    const int*   mask     = (const int*)d_in[16];
    float* out = (float*)d_out;

    float* sc = nullptr;
    cudaGetSymbolAddress((void**)&sc, g_scratch);
    int* acnt = (int*)(sc + S_ACNT);

    cudaFuncSetAttribute(segsum3_kernel,
                         cudaFuncAttributeMaxDynamicSharedMemorySize, SEG3_SMEM_BYTES);

    // 1-2. area histogram
    zero_acnt<<<1, 516>>>(acnt);
    hist_kernel<<<dim3(4, 16), 256>>>(mask, acnt);
    // 3. atomic-free segment sums
    segsum3_kernel<<<dim3(12, 4, 3), 256, SEG3_SMEM_BYTES>>>(hd1, h1, mask,
                                                             sc + S_PART, sc + S_GLP);
    // 4. everything else: persistent kernel, 2 CTAs/SM, grid barriers
    chain_mega<<<NB, 256>>>(ref_orig, embed_w, comp_w1, comp_w2, hist_w1, hist_w2,
                            genes_w1, genes_w2, wref_w1, wref_w2,
                            ca_wq, ca_wk, ca_wv, ca_wo, sc, out);
}

// round 17
// speedup vs baseline: 1.3721x; 1.3721x over previous
#include <cuda_runtime.h>
#include <stdint.h>
#include <math.h>

#define HW    65536
#define EE    256
#define GG    512
#define NCC   16
#define NB    296

// ---- scratch layout (floats), all regions write-once per launch ----
#define S_PART 0            // segsum partials [3][4][129][384] = 594432
#define S_GLP  594432       // glob partials [3][4][384] = 4608
#define S_ACNT 599040       // area counts (int) [4][129] pad 1024
#define S_AF   600064       // allfv  [512][768] = 393216
#define S_EM   993280       // emb    [512][256] = 131072
#define S_CP   1124352      // comp   [4][16] pad 1024
#define S_HH4  1125376      // hidden [4][512][256] = 524288
#define S_RW   1649664      // rw     [3][512][64] = 98304
#define S_OB   2534400      // ob     [3][4][256] = 3072
#define S_OW   2537472      // obwo   [3][4][512] = 6144
#define S_OE   2543616      // post-relu out_exprs[0] copy = 262144
#define P_EMB  2805760      // emb split-K partials 4*131072 = 524288
#define P_RW   3330048      // rw partials 24*32768 = 786432
#define P_GEN  4116480      // genes partials 4*131072 = 524288
#define P_KV   4640768      // kf/vf partials 12*131072 = 1572864
#define SCRATCH_FLOATS 6213632

__device__ float g_scratch[SCRATCH_FLOATS];

// ---- d_out layout (floats) ----
#define O_OCT  0
#define O_OE0  8192
#define O_OCTE 794624
#define O_GH   802816
#define O_CMP  933888
#define O_ARE  933952

// ============================================================
// software grid barrier (monotonic epochs; all NB blocks resident)
// ============================================================
__device__ unsigned long long g_bar_arrive = 0ULL;
__device__ volatile unsigned long long g_bar_release = 0ULL;

__device__ __forceinline__ void grid_bar()
{
    __syncthreads();
    __threadfence();
    if (threadIdx.x == 0) {
        unsigned long long t = atomicAdd(&g_bar_arrive, 1ULL);
        unsigned long long epoch = t / NB + 1ULL;
        if ((t % NB) == (unsigned long long)(NB - 1)) {
            g_bar_release = epoch;
            __threadfence();
        } else {
            while (g_bar_release < epoch) { }
            __threadfence();
        }
    }
    __syncthreads();
}

// ============================================================
// segsum helpers (cp.async)
// ============================================================
#define W2_T0  4128
#define W2_T1  5184
#define W2_I0  6240
#define W2_I1  6272
#define W2_SZ  6304
#define SEG3_SMEM_BYTES (8 * W2_SZ * 4)

__device__ __forceinline__ uint32_t smem_u32(const void* p)
{
    uint32_t a;
    asm("{ .reg .u64 t; cvta.to.shared.u64 t, %1; cvt.u32.u64 %0, t; }"
        : "=r"(a) : "l"(p));
    return a;
}
__device__ __forceinline__ void cpa4(uint32_t dst, const void* src)
{
    asm volatile("cp.async.ca.shared.global [%0], [%1], 4;" :: "r"(dst), "l"(src));
}
#define CPA_COMMIT() asm volatile("cp.async.commit_group;")
#define CPA_WAIT1()  asm volatile("cp.async.wait_group 1;")
#define CPA_WAIT0()  asm volatile("cp.async.wait_group 0;")

// ============================================================
// segsum (unchanged: ~124us, DRAM-bound)
// ============================================================
__global__ void __launch_bounds__(256, 1)
segsum3_kernel(const float* __restrict__ hd1,
               const float* __restrict__ h1,
               const int* __restrict__ mask,
               float* __restrict__ partial,
               float* __restrict__ globpart)
{
    extern __shared__ float smem[];
    int cg = blockIdx.x, b = blockIdx.y, ps = blockIdx.z;
    int tid = threadIdx.x, lane = tid & 31, w = tid >> 5;

    for (int i = tid; i < 8 * W2_SZ; i += 256) smem[i] = 0.f;
    __syncthreads();

    const float* base = (cg < 8)
        ? hd1 + (((size_t)b * 256 + cg * 32) << 16)
        : h1  + (((size_t)b * 128 + (cg - 8) * 32) << 16);
    const int* mp = mask + ((size_t)b << 16);

    float* acc  = smem + w * W2_SZ;
    float* tile0 = smem + w * W2_SZ + W2_T0;
    float* tile1 = smem + w * W2_SZ + W2_T1;
    int*   ids0 = (int*)(smem + w * W2_SZ + W2_I0);
    int*   ids1 = (int*)(smem + w * W2_SZ + W2_I1);
    uint32_t tB0 = smem_u32(tile0), tB1 = smem_u32(tile1);
    uint32_t iB0 = smem_u32(ids0),  iB1 = smem_u32(ids1);

    int L = lane * 129;
    int T = lane * 33;
    float tot = 0.f;

    int tb = ps * 683;
    int te = (ps < 2) ? tb + 683 : 2048;
    int t0 = tb + w;
    int cnt = (t0 < te) ? (te - t0 + 7) / 8 : 0;

#define SEG_PREFETCH(tt, TB, IB)                                        \
    do {                                                                \
        const float* cp_ = base + (tt) * 32 + lane;                     \
        uint32_t td_ = (TB) + lane * 4;                                 \
        _Pragma("unroll")                                               \
        for (int c_ = 0; c_ < 32; c_++)                                 \
            cpa4(td_ + c_ * (33 * 4), cp_ + ((size_t)c_ << 16));        \
        cpa4((IB) + lane * 4, mp + (tt) * 32 + lane);                   \
    } while (0)

    if (cnt > 0) { SEG_PREFETCH(t0, tB0, iB0); CPA_COMMIT(); }

    for (int i = 0; i < cnt; i++) {
        int cur = i & 1;
        if (i + 1 < cnt) {
            int tn = t0 + (i + 1) * 8;
            if ((i + 1) & 1) SEG_PREFETCH(tn, tB1, iB1);
            else             SEG_PREFETCH(tn, tB0, iB0);
            CPA_COMMIT();
            CPA_WAIT1();
        } else {
            CPA_WAIT0();
        }
        __syncwarp();
        const float* tile = cur ? tile1 : tile0;
        const int*   ids  = cur ? ids1  : ids0;
#pragma unroll
        for (int p = 0; p < 32; p += 4) {
            int i0 = ids[p], i1 = ids[p + 1], i2 = ids[p + 2], i3 = ids[p + 3];
            float t0v = tile[T + p],     t1v = tile[T + p + 1];
            float t2v = tile[T + p + 2], t3v = tile[T + p + 3];
            tot += (t0v + t1v) + (t2v + t3v);
            bool u1 = (i1 != i0);
            bool u2 = (i2 != i0) && (i2 != i1);
            bool u3 = (i3 != i0) && (i3 != i1) && (i3 != i2);
            if (!u3) { if (i3 == i0) t0v += t3v; else if (i3 == i1) t1v += t3v; else t2v += t3v; }
            if (!u2) { if (i2 == i0) t0v += t2v; else t1v += t2v; }
            if (!u1) t0v += t1v;
            float a0 = acc[L + i0] + t0v;
            float a1 = u1 ? acc[L + i1] + t1v : 0.f;
            float a2 = u2 ? acc[L + i2] + t2v : 0.f;
            float a3 = u3 ? acc[L + i3] + t3v : 0.f;
            acc[L + i0] = a0;
            if (u1) acc[L + i1] = a1;
            if (u2) acc[L + i2] = a2;
            if (u3) acc[L + i3] = a3;
        }
        __syncwarp();
    }
#undef SEG_PREFETCH

    __syncwarp();
    ((float*)ids0)[lane] = tot;
    __syncthreads();

    if (tid < 32) {
        float s = 0.f;
#pragma unroll
        for (int ww = 0; ww < 8; ww++) s += smem[ww * W2_SZ + W2_I0 + tid];
        globpart[(size_t)(ps * 4 + b) * 384 + cg * 32 + tid] = s;
    }

    float* outp = partial + ((size_t)(ps * 4 + b) * 129 * 384) + cg * 32;
    for (int i = tid; i < 129 * 32; i += 256) {
        int cell = i >> 5, ch = i & 31;
        float s = 0.f;
#pragma unroll
        for (int ww = 0; ww < 8; ww++) s += smem[ww * W2_SZ + ch * 129 + cell];
        outp[(size_t)cell * 384 + ch] = s;
    }
}

// ============================================================
__global__ void zero_acnt(int* __restrict__ cnt)
{
    int i = threadIdx.x;
    if (i < 516) cnt[i] = 0;
}

__global__ void hist_kernel(const int* __restrict__ mask, int* __restrict__ cnt)
{
    int b = blockIdx.x, ch = blockIdx.y, tid = threadIdx.x;
    __shared__ int h[129];
    if (tid < 129) h[tid] = 0;
    __syncthreads();
    const int* mp = mask + ((size_t)b << 16) + ch * 4096;
    for (int i = tid; i < 4096; i += 256)
        atomicAdd(&h[mp[i]], 1);
    __syncthreads();
    if (tid < 129 && h[tid]) atomicAdd(&cnt[b * 129 + tid], h[tid]);
}

// ============================================================
// device GEMM tile: 64x64 output, BK=16, 4x4 microtile, prefetch.
// R13-proven version: single buffer, TWO __syncthreads per slab.
// gs = 2048 floats.
// ============================================================
__device__ void gemm_tile(const float* __restrict__ A, int lda,
                          const float* __restrict__ B, int ldb,
                          float* __restrict__ C, int ldc,
                          int K, int relu, int row0, int col0, float* gs)
{
    __syncthreads();   // protect smem vs previous job
    int tid = threadIdx.x;
    int tx = tid & 15, ty = tid >> 4;
    int arow = tid >> 2, ak4 = (tid & 3) * 4;
    int brow = tid >> 4, bc4 = (tid & 15) * 4;
    float* As = gs;
    float* Bs = gs + 1024;

    const float* Ap = A + (size_t)(row0 + arow) * lda + ak4;
    const float* Bp = B + (size_t)brow * ldb + col0 + bc4;

    float acc[4][4] = {};
    float4 av = *(const float4*)(Ap);
    float4 bv = *(const float4*)(Bp);
    for (int k0 = 0; k0 < K; k0 += 16) {
        As[(ak4 + 0) * 64 + arow] = av.x;
        As[(ak4 + 1) * 64 + arow] = av.y;
        As[(ak4 + 2) * 64 + arow] = av.z;
        As[(ak4 + 3) * 64 + arow] = av.w;
        *(float4*)&Bs[brow * 64 + bc4] = bv;
        __syncthreads();
        if (k0 + 16 < K) {
            av = *(const float4*)(Ap + k0 + 16);
            bv = *(const float4*)(Bp + (size_t)(k0 + 16) * ldb);
        }
#pragma unroll
        for (int k = 0; k < 16; k++) {
            float4 a = *(const float4*)&As[k * 64 + ty * 4];
            float4 b = *(const float4*)&Bs[k * 64 + tx * 4];
            acc[0][0] += a.x * b.x; acc[0][1] += a.x * b.y; acc[0][2] += a.x * b.z; acc[0][3] += a.x * b.w;
            acc[1][0] += a.y * b.x; acc[1][1] += a.y * b.y; acc[1][2] += a.y * b.z; acc[1][3] += a.y * b.w;
            acc[2][0] += a.z * b.x; acc[2][1] += a.z * b.y; acc[2][2] += a.z * b.z; acc[2][3] += a.z * b.w;
            acc[3][0] += a.w * b.x; acc[3][1] += a.w * b.y; acc[3][2] += a.w * b.z; acc[3][3] += a.w * b.w;
        }
        __syncthreads();
    }
#pragma unroll
    for (int i = 0; i < 4; i++) {
        float4 v = make_float4(acc[i][0], acc[i][1], acc[i][2], acc[i][3]);
        if (relu) {
            v.x = fmaxf(v.x, 0.f); v.y = fmaxf(v.y, 0.f);
            v.z = fmaxf(v.z, 0.f); v.w = fmaxf(v.w, 0.f);
        }
        *(float4*)&C[(size_t)(row0 + ty * 4 + i) * ldc + col0 + tx * 4] = v;
    }
}

// ============================================================
// device N16 GEMM: 32 rows x 16 cols, K multiple of 64; buf = 2048 floats.
// ============================================================
__device__ void gemmN16_dev(const float* __restrict__ A, const float* __restrict__ B,
                            float* __restrict__ C, int K, int row0, float* buf)
{
    int tid = threadIdx.x;
    int r = tid >> 3, cg = tid & 7, c0 = cg * 2;
    float s0 = 0.f, s1 = 0.f;
    for (int kb = 0; kb < K; kb += 64) {
        __syncthreads();
        for (int i = tid; i < 2048; i += 256) {
            int rr = i >> 6, kk = i & 63;
            buf[i] = A[(size_t)(row0 + rr) * K + kb + kk];
        }
        __syncthreads();
        const float* ar = buf + r * 64;
#pragma unroll 4
        for (int k = 0; k < 64; k++) {
            float a = ar[k];
            s0 += a * B[(kb + k) * 16 + c0];
            s1 += a * B[(kb + k) * 16 + c0 + 1];
        }
    }
    C[(size_t)(row0 + r) * 16 + c0]     = s0;
    C[(size_t)(row0 + r) * 16 + c0 + 1] = s1;
    __syncthreads();
}

// ============================================================
__device__ void embp_comp_dev(const float* __restrict__ emb,
                              const float* __restrict__ w1, const float* __restrict__ w2,
                              float* __restrict__ comp, float* __restrict__ comp_out,
                              int b, float* xs)
{
    __syncthreads();
    int tid = threadIdx.x;
    float* ep = xs;
    float* t1 = xs + 256;
    float* t2 = xs + 512;
    float s0 = 0.f;
    for (int i = 0; i < 128; i++)
        s0 += emb[(size_t)(b * 128 + i) * EE + tid];
    ep[tid] = s0 * (1.f / 128.f);
    __syncthreads();
    float s = 0.f;
    for (int c = 0; c < EE; c++)
        s += ep[c] * w1[(size_t)c * EE + tid];
    t1[tid] = fmaxf(s, 0.f);
    __syncthreads();
    if (tid < NCC) {
        float s2 = 0.f;
        for (int j = 0; j < EE; j++)
            s2 += t1[j] * w2[(size_t)j * NCC + tid];
        t2[tid] = s2;
    }
    __syncthreads();
    if (tid == 0) {
        float m = t2[0];
        for (int o = 1; o < NCC; o++) m = fmaxf(m, t2[o]);
        float tot = 0.f;
        float e[NCC];
        for (int o = 0; o < NCC; o++) { e[o] = expf(t2[o] - m); tot += e[o]; }
        float inv = 1.f / tot;
        for (int o = 0; o < NCC; o++) {
            comp[b * NCC + o] = e[o] * inv;
            comp_out[b * NCC + o] = e[o] * inv;
        }
    }
    __syncthreads();
}

// ============================================================
__device__ void reduce_softmax_dev(const float* __restrict__ P, float* __restrict__ rw,
                                   int job, float* xs)
{
    __syncthreads();
    int tid = threadIdx.x;
    int row = job * 4 + (tid >> 6);
    int col = tid & 63;
    int br = row >> 9, lr = row & 511;
    const float* p = P + (size_t)br * 8 * 32768 + (size_t)lr * 64 + col;
    float s = 0.f;
#pragma unroll
    for (int j = 0; j < 8; j++) s += p[(size_t)j * 32768];

    int lane = tid & 31, half = (tid >> 5) & 1, r4 = tid >> 6;
    float* mm = xs;
    float* ss = xs + 8;
    float m = s;
    for (int o = 16; o; o >>= 1) m = fmaxf(m, __shfl_xor_sync(0xffffffffu, m, o));
    if (lane == 0) mm[r4 * 2 + half] = m;
    __syncthreads();
    m = fmaxf(mm[r4 * 2], mm[r4 * 2 + 1]);
    float e = expf(s - m);
    float t = e;
    for (int o = 16; o; o >>= 1) t += __shfl_xor_sync(0xffffffffu, t, o);
    if (lane == 0) ss[r4 * 2 + half] = t;
    __syncthreads();
    t = ss[r4 * 2] + ss[r4 * 2 + 1];
    rw[(size_t)row * 64 + col] = e / t;
    __syncthreads();
}

// ============================================================
// attention with fused kf/vf split-K reduce (R16-proven correctness).
// pkv slice layout: (mat*6 + br*2 + kc) * 131072, element (kn*256 + ch).
// ============================================================
__device__ void attn_dev(const float* __restrict__ comp,
                         const float* __restrict__ ca_wq,
                         const float* __restrict__ pkv,
                         float* __restrict__ ob,
                         int b, int h, int br, float* xs)
{
    __syncthreads();
    int tid = threadIdx.x, lane = tid & 31, warp = tid >> 5;
    const float* wq = ca_wq + (size_t)br * 16 * EE;
    const float* k0 = pkv + (size_t)(br * 2 + 0) * 131072;
    const float* k1 = pkv + (size_t)(br * 2 + 1) * 131072;
    const float* v0 = pkv + (size_t)(6 + br * 2 + 0) * 131072;
    const float* v1 = pkv + (size_t)(6 + br * 2 + 1) * 131072;

    float* q   = xs;
    float* scv = xs + 32;
    float* r1  = xs + 544;
    float* prt = xs + 800;

    if (tid < 32) {
        float s = 0.f;
        for (int c = 0; c < NCC; c++)
            s += comp[b * NCC + c] * wq[(size_t)c * EE + h * 32 + tid];
        q[tid] = s * 0.17677669529663687f;
    }
    __syncthreads();

    for (int kk = 0; kk < 64; kk++) {
        int kn = warp * 64 + kk;
        size_t idx = (size_t)kn * EE + h * 32 + lane;
        float p = q[lane] * (k0[idx] + k1[idx]);
        for (int off = 16; off; off >>= 1) p += __shfl_down_sync(0xffffffff, p, off);
        if (lane == 0) scv[kn] = p;
    }
    __syncthreads();

    float m = fmaxf(scv[tid], scv[tid + 256]);
    r1[tid] = m; __syncthreads();
    for (int s = 128; s > 0; s >>= 1) { if (tid < s) r1[tid] = fmaxf(r1[tid], r1[tid + s]); __syncthreads(); }
    float maxv = r1[0]; __syncthreads();
    float e0 = expf(scv[tid] - maxv), e1 = expf(scv[tid + 256] - maxv);
    scv[tid] = e0; scv[tid + 256] = e1;
    r1[tid] = e0 + e1; __syncthreads();
    for (int s = 128; s > 0; s >>= 1) { if (tid < s) r1[tid] += r1[tid + s]; __syncthreads(); }
    float invs = 1.f / r1[0];

    float a = 0.f;
    for (int kn = warp; kn < 512; kn += 8) {
        size_t idx = (size_t)kn * EE + h * 32 + lane;
        a += scv[kn] * (v0[idx] + v1[idx]);
    }
    prt[warp * 32 + lane] = a;
    __syncthreads();
    if (tid < 32) {
        float s = 0.f;
        for (int w = 0; w < 8; w++) s += prt[w * 32 + tid];
        ob[((size_t)br * 4 + b) * EE + h * 32 + tid] = s * invs;
    }
    __syncthreads();
}

// ============================================================
__device__ void obwo_dev(const float* __restrict__ ob, const float* __restrict__ ca_wo,
                         float* __restrict__ obwo, int j, float* xs)
{
    __syncthreads();
    int idx = j >> 1, half = j & 1;
    int br = idx >> 2;
    int tid = threadIdx.x;
    xs[tid] = ob[(size_t)idx * EE + tid];
    __syncthreads();
    const float* wo = ca_wo + (size_t)br * EE * GG;
    int col = half * 256 + tid;
    float s = 0.f;
    for (int c = 0; c < EE; c++)
        s += xs[c] * wo[(size_t)c * GG + col];
    obwo[(size_t)idx * GG + col] = s;
    __syncthreads();
}

// ============================================================
// Persistent chain megakernel, 296 blocks (2 CTAs/SM), R13 structure.
// ============================================================
__global__ void __launch_bounds__(256, 2)
chain_mega(const float* __restrict__ ref_orig, const float* __restrict__ embed_w,
           const float* __restrict__ comp_w1, const float* __restrict__ comp_w2,
           const float* __restrict__ hist_w1, const float* __restrict__ hist_w2,
           const float* __restrict__ genes_w1, const float* __restrict__ genes_w2,
           const float* __restrict__ wref_w1, const float* __restrict__ wref_w2,
           const float* __restrict__ ca_wq, const float* __restrict__ ca_wk,
           const float* __restrict__ ca_wv, const float* __restrict__ ca_wo,
           float* __restrict__ g, float* __restrict__ out)
{
    __shared__ float gs[2048];
    __shared__ float xs[1088];
    int tid = threadIdx.x;
    const int* acnt = (const int*)(g + S_ACNT);

    // ---- finalize (allfv + area), 512 jobs ----
    for (int n = blockIdx.x; n < 512; n += NB) {
        int b = n >> 7, cell = n & 127;
        int a = acnt[b * 129 + cell + 1];
        if (tid == 0) out[O_ARE + n] = (float)a;
        float inva = 1.f / fmaxf((float)a, 1.f);
        const size_t PS = (size_t)4 * 129 * 384;
        size_t rp0 = (size_t)b * 129 * 384 + (size_t)(cell + 1) * 384;
        for (int j = tid; j < 768; j += 256) {
            float v;
            if (j < 384) {
                v = (g[S_PART + rp0 + j] + g[S_PART + rp0 + PS + j]
                   + g[S_PART + rp0 + 2 * PS + j]) * inva;
            } else {
                int c = j - 384;
                v = (g[S_GLP + (size_t)b * 384 + c] + g[S_GLP + (size_t)(4 + b) * 384 + c]
                   + g[S_GLP + (size_t)(8 + b) * 384 + c]) * (1.f / 65536.f);
            }
            g[S_AF + (size_t)n * 768 + j] = v;
        }
    }
    grid_bar();

    // ---- emb GEMM, split-K 4 (128 jobs) ----
    for (int j = blockIdx.x; j < 128; j += NB) {
        int kc = j >> 5, t = j & 31;
        gemm_tile(g + S_AF + kc * 192, 768, embed_w + (size_t)kc * 192 * 256, 256,
                  g + P_EMB + (size_t)kc * 131072, 256, 192, 0,
                  (t >> 2) * 64, (t & 3) * 64, gs);
    }
    grid_bar();

    // ---- emb reduce (512 jobs) ----
    for (int j = blockIdx.x; j < 512; j += NB) {
        int i = j * 256 + tid;
        g[S_EM + i] = g[P_EMB + i] + g[P_EMB + 131072 + i]
                    + g[P_EMB + 262144 + i] + g[P_EMB + 393216 + i];
    }
    grid_bar();

    // ---- hidden (128 jobs, K=256 direct, relu) + embp_comp (4 jobs) ----
    for (int j = blockIdx.x; j < 132; j += NB) {
        if (j < 128) {
            int zz = j >> 5, t = j & 31;
            const float* B = (zz == 0) ? hist_w1 : wref_w1 + (size_t)(zz - 1) * 65536;
            gemm_tile(g + S_EM, 256, B, 256, g + S_HH4 + (size_t)zz * 131072, 256,
                      256, 1, (t >> 2) * 64, (t & 3) * 64, gs);
        } else {
            embp_comp_dev(g + S_EM, comp_w1, comp_w2, g + S_CP, out + O_CMP, j - 128, xs);
        }
    }
    grid_bar();

    // ---- out_cell_type (16 jobs) + rw logits split-K 8 (192 jobs) ----
    for (int j = blockIdx.x; j < 208; j += NB) {
        if (j < 16) {
            gemmN16_dev(g + S_HH4, hist_w2, out + O_OCT, 256, j * 32, gs);
        } else {
            int q = j - 16;
            int br = q / 64, rr = q - br * 64, kc = rr >> 3, mt = rr & 7;
            gemm_tile(g + S_HH4 + (size_t)(1 + br) * 131072 + kc * 32, 256,
                      wref_w2 + (size_t)br * 16384 + (size_t)kc * 32 * 64, 64,
                      g + P_RW + (size_t)(br * 8 + kc) * 32768, 64, 32, 0,
                      mt * 64, 0, gs);
        }
    }
    grid_bar();

    // ---- rw reduce + softmax (384 jobs) ----
    for (int j = blockIdx.x; j < 384; j += NB)
        reduce_softmax_dev(g + P_RW, g + S_RW, j, xs);
    grid_bar();

    // ---- refw (192 jobs, K=64) -> out_exprs pre-relu ----
    for (int j = blockIdx.x; j < 192; j += NB) {
        int br = j / 64, t = j - br * 64;
        gemm_tile(g + S_RW + (size_t)br * 32768, 64, ref_orig, 512,
                  out + O_OE0 + (size_t)br * 262144, 512, 64, 0,
                  (t >> 3) * 64, (t & 7) * 64, gs);
    }
    grid_bar();

    // ---- kf/vf split-K 2 (384 jobs) -> P_KV partials ----
    for (int j = blockIdx.x; j < 384; j += NB) {
        int mat = j / 192, rr = j - mat * 192;
        int br = rr / 64, rr2 = rr - br * 64;
        int kc = rr2 >> 5, t = rr2 & 31;
        const float* B = (mat ? ca_wv : ca_wk) + (size_t)br * 131072 + (size_t)kc * 256 * 256;
        gemm_tile(out + O_OE0 + (size_t)br * 262144 + kc * 256, 512, B, 256,
                  g + P_KV + (size_t)(mat * 6 + br * 2 + kc) * 131072, 256,
                  256, 0, (t >> 2) * 64, (t & 3) * 64, gs);
    }
    grid_bar();

    // ---- attention (96 jobs), kf/vf reduce fused inline ----
    for (int j = blockIdx.x; j < 96; j += NB)
        attn_dev(g + S_CP, ca_wq, g + P_KV, g + S_OB,
                 j & 3, (j >> 2) & 7, j >> 5, xs);
    grid_bar();

    // ---- obwo (24 jobs) ----
    for (int j = blockIdx.x; j < 24; j += NB)
        obwo_dev(g + S_OB, ca_wo, g + S_OW, j, xs);
    grid_bar();

    // ---- addrelu (3072 jobs); branch0 copy to S_OE ----
    for (int j = blockIdx.x; j < 3072; j += NB) {
        int i = j * 256 + tid;
        int br = i >> 18;
        int rem = i & 262143;
        int gg2 = rem & 511, n = rem >> 9, b = n >> 7;
        float v = out[O_OE0 + i] + g[S_OW + (size_t)(br * 4 + b) * 512 + gg2];
        v = fmaxf(v, 0.f);
        out[O_OE0 + i] = v;
        if (br == 0) g[S_OE + rem] = v;
    }
    grid_bar();

    // ---- genes GEMM split-K 4 (128 jobs) ----
    for (int j = blockIdx.x; j < 128; j += NB) {
        int kc = j >> 5, t = j & 31;
        gemm_tile(g + S_OE + kc * 128, 512, genes_w1 + (size_t)kc * 128 * 256, 256,
                  g + P_GEN + (size_t)kc * 131072, 256, 128, 0,
                  (t >> 2) * 64, (t & 3) * 64, gs);
    }
    grid_bar();

    // ---- genes reduce + relu (512 jobs) ----
    for (int j = blockIdx.x; j < 512; j += NB) {
        int i = j * 256 + tid;
        float s = g[P_GEN + i] + g[P_GEN + 131072 + i]
                + g[P_GEN + 262144 + i] + g[P_GEN + 393216 + i];
        out[O_GH + i] = fmaxf(s, 0.f);
    }
    grid_bar();

    // ---- out_cell_type_expr (16 jobs) ----
    for (int j = blockIdx.x; j < 16; j += NB)
        gemmN16_dev(out + O_GH, genes_w2, out + O_OCTE, 256, j * 32, gs);
}

// ============================================================
extern "C" void kernel_launch(void* const* d_in, const int* in_sizes, int n_in,
                              void* d_out, int out_size)
{
    (void)in_sizes; (void)n_in; (void)out_size;
    const float* hd1      = (const float*)d_in[0];
    const float* h1       = (const float*)d_in[1];
    const float* ref_orig = (const float*)d_in[2];
    const float* embed_w  = (const float*)d_in[3];
    const float* comp_w1  = (const float*)d_in[4];
    const float* comp_w2  = (const float*)d_in[5];
    const float* hist_w1  = (const float*)d_in[6];
    const float* hist_w2  = (const float*)d_in[7];
    const float* genes_w1 = (const float*)d_in[8];
    const float* genes_w2 = (const float*)d_in[9];
    const float* wref_w1  = (const float*)d_in[10];
    const float* wref_w2  = (const float*)d_in[11];
    const float* ca_wq    = (const float*)d_in[12];
    const float* ca_wk    = (const float*)d_in[13];
    const float* ca_wv    = (const float*)d_in[14];
    const float* ca_wo    = (const float*)d_in[15];
    const int*   mask     = (const int*)d_in[16];
    float* out = (float*)d_out;

    float* sc = nullptr;
    cudaGetSymbolAddress((void**)&sc, g_scratch);
    int* acnt = (int*)(sc + S_ACNT);

    cudaFuncSetAttribute(segsum3_kernel,
                         cudaFuncAttributeMaxDynamicSharedMemorySize, SEG3_SMEM_BYTES);

    // 1-2. area histogram
    zero_acnt<<<1, 516>>>(acnt);
    hist_kernel<<<dim3(4, 16), 256>>>(mask, acnt);
    // 3. atomic-free segment sums
    segsum3_kernel<<<dim3(12, 4, 3), 256, SEG3_SMEM_BYTES>>>(hd1, h1, mask,
                                                             sc + S_PART, sc + S_GLP);
    // 4. everything else: persistent kernel, 2 CTAs/SM, grid barriers
    chain_mega<<<NB, 256>>>(ref_orig, embed_w, comp_w1, comp_w2, hist_w1, hist_w2,
                            genes_w1, genes_w2, wref_w1, wref_w2,
                            ca_wq, ca_wk, ca_wv, ca_wo, sc, out);
}